// round 5
// baseline (speedup 1.0000x reference)
#include <cuda_runtime.h>
#include <cstdint>

// Problem shape (fixed by dataset): N=50000 nodes, E=800000, K=8, D=64.
#define DDIM 64
#define MAX_NODES 50000
#define MAX_RELS 8
#define MAX_EDGES 800000

// Scratch: hw[n][k][o] (102.4 MB) + CSR build arrays.
__device__ float g_hw[(size_t)MAX_NODES * MAX_RELS * DDIM];
__device__ int g_deg[MAX_NODES];
__device__ int g_rowptr[MAX_NODES + 1];
__device__ int g_cursor[MAX_NODES];
__device__ int g_eperm[MAX_EDGES];

// ---------------------------------------------------------------------------
// 64x64-tile fp32 GEMM (identical to the round-1 kernel that passed):
// out[n][o] (+ bias[o]) = sum_d A[n][d] * B[k][d][o]
// grid.x tiles nodes (64/block), grid.y = relation k.
// out_param == nullptr -> write g_hw with row_stride = n_rels*64.
// ---------------------------------------------------------------------------
__global__ __launch_bounds__(256) void rgcn_gemm_kernel(
    const float* __restrict__ A,     // [n_rows][64]
    const float* __restrict__ Ball,  // [gridDim.y][64][64]
    const float* __restrict__ bias,  // [64] or nullptr
    float* __restrict__ out_param,   // nullptr -> g_hw
    int n_rows, int row_stride)
{
    __shared__ float As[64][65];
    __shared__ float Bs[64][65];

    float* out = out_param ? out_param : g_hw;
    const float* B = Ball + (size_t)blockIdx.y * DDIM * DDIM;
    const int colbase = blockIdx.y * DDIM;
    const int n0 = blockIdx.x * 64;
    const int tid = threadIdx.x;

#pragma unroll
    for (int i = 0; i < 16; ++i) {
        int idx = tid + i * 256;
        int r = idx >> 6;
        int c = idx & 63;
        int gr = n0 + r;
        As[c][r] = (gr < n_rows) ? A[(size_t)gr * DDIM + c] : 0.0f;
        Bs[r][c] = B[idx];
    }
    __syncthreads();

    const int ty = tid >> 4;
    const int tx = tid & 15;

    float acc[4][4] = {};
#pragma unroll 16
    for (int d = 0; d < 64; ++d) {
        float a0 = As[d][ty * 4 + 0];
        float a1 = As[d][ty * 4 + 1];
        float a2 = As[d][ty * 4 + 2];
        float a3 = As[d][ty * 4 + 3];
        float b0 = Bs[d][tx * 4 + 0];
        float b1 = Bs[d][tx * 4 + 1];
        float b2 = Bs[d][tx * 4 + 2];
        float b3 = Bs[d][tx * 4 + 3];
        acc[0][0] += a0 * b0; acc[0][1] += a0 * b1; acc[0][2] += a0 * b2; acc[0][3] += a0 * b3;
        acc[1][0] += a1 * b0; acc[1][1] += a1 * b1; acc[1][2] += a1 * b2; acc[1][3] += a1 * b3;
        acc[2][0] += a2 * b0; acc[2][1] += a2 * b1; acc[2][2] += a2 * b2; acc[2][3] += a2 * b3;
        acc[3][0] += a3 * b0; acc[3][1] += a3 * b1; acc[3][2] += a3 * b2; acc[3][3] += a3 * b3;
    }

    float bb[4] = {0.f, 0.f, 0.f, 0.f};
    if (bias) {
        bb[0] = bias[tx * 4 + 0];
        bb[1] = bias[tx * 4 + 1];
        bb[2] = bias[tx * 4 + 2];
        bb[3] = bias[tx * 4 + 3];
    }

#pragma unroll
    for (int i = 0; i < 4; ++i) {
        int gr = n0 + ty * 4 + i;
        if (gr < n_rows) {
            float4 v;
            v.x = acc[i][0] + bb[0];
            v.y = acc[i][1] + bb[1];
            v.z = acc[i][2] + bb[2];
            v.w = acc[i][3] + bb[3];
            *(float4*)&out[(size_t)gr * row_stride + colbase + tx * 4] = v;
        }
    }
}

// ---------------------------------------------------------------------------
// CSR build: zero -> histogram -> single-block scan -> cursor copy -> scatter
// ---------------------------------------------------------------------------
__global__ void zero_deg_kernel(int n_nodes)
{
    int i = blockIdx.x * blockDim.x + threadIdx.x;
    if (i < n_nodes) g_deg[i] = 0;
}

__global__ void hist_kernel(const int* __restrict__ dst, int n_edges)
{
    int e = blockIdx.x * blockDim.x + threadIdx.x;
    if (e < n_edges) atomicAdd(&g_deg[dst[e]], 1);
}

// Exclusive prefix sum over g_deg -> g_rowptr. Single block, 1024 threads.
__global__ __launch_bounds__(1024) void scan_kernel(int n_nodes)
{
    __shared__ int sm[1024];
    __shared__ int carry_s;
    int t = threadIdx.x;
    if (t == 0) { carry_s = 0; g_rowptr[0] = 0; }
    __syncthreads();

    for (int base = 0; base < n_nodes; base += 1024) {
        int v = (base + t < n_nodes) ? g_deg[base + t] : 0;
        sm[t] = v;
        __syncthreads();
#pragma unroll
        for (int off = 1; off < 1024; off <<= 1) {
            int x = (t >= off) ? sm[t - off] : 0;
            __syncthreads();
            sm[t] += x;
            __syncthreads();
        }
        int carry = carry_s;
        if (base + t < n_nodes) g_rowptr[base + t + 1] = carry + sm[t];
        __syncthreads();
        if (t == 0) carry_s = carry + sm[1023];
        __syncthreads();
    }
}

__global__ void cursor_kernel(int n_nodes)
{
    int i = blockIdx.x * blockDim.x + threadIdx.x;
    if (i < n_nodes) g_cursor[i] = g_rowptr[i];
}

__global__ void scatter_kernel(const int* __restrict__ dst, int n_edges)
{
    int e = blockIdx.x * blockDim.x + threadIdx.x;
    if (e >= n_edges) return;
    int pos = atomicAdd(&g_cursor[dst[e]], 1);
    g_eperm[pos] = e;
}

// ---------------------------------------------------------------------------
// Aggregation: one warp per dst node. acc = sum_{e in seg} hw[src_e,r_e]*norm_e
// out[n] = relu(out[n] (= loop term + bias) + acc). No atomics, relu fused.
// Each lane owns 2 floats (float2 at lane offset) -> 256B coalesced gathers.
// ---------------------------------------------------------------------------
__global__ __launch_bounds__(256) void agg_kernel(
    const float* __restrict__ norm, const int* __restrict__ src,
    const int* __restrict__ rel, float* __restrict__ out, int n_nodes)
{
    int warp = (blockIdx.x * 256 + threadIdx.x) >> 5;
    int lane = threadIdx.x & 31;
    if (warp >= n_nodes) return;

    int beg = g_rowptr[warp];
    int end = g_rowptr[warp + 1];

    float ax = 0.f, ay = 0.f;
    int i = beg;
    // 2-way unrolled for memory-level parallelism
    for (; i + 1 < end; i += 2) {
        int e0 = g_eperm[i];
        int e1 = g_eperm[i + 1];
        int s0 = src[e0], r0 = rel[e0];
        int s1 = src[e1], r1 = rel[e1];
        float n0 = norm[e0];
        float n1 = norm[e1];
        const float2* row0 = (const float2*)(g_hw + ((size_t)s0 * MAX_RELS + r0) * DDIM);
        const float2* row1 = (const float2*)(g_hw + ((size_t)s1 * MAX_RELS + r1) * DDIM);
        float2 v0 = row0[lane];
        float2 v1 = row1[lane];
        ax += v0.x * n0; ay += v0.y * n0;
        ax += v1.x * n1; ay += v1.y * n1;
    }
    if (i < end) {
        int e0 = g_eperm[i];
        int s0 = src[e0], r0 = rel[e0];
        float n0 = norm[e0];
        const float2* row0 = (const float2*)(g_hw + ((size_t)s0 * MAX_RELS + r0) * DDIM);
        float2 v0 = row0[lane];
        ax += v0.x * n0; ay += v0.y * n0;
    }

    float2* o = (float2*)(out + (size_t)warp * DDIM);
    float2 base = o[lane];
    o[lane] = make_float2(fmaxf(base.x + ax, 0.0f), fmaxf(base.y + ay, 0.0f));
}

// ---------------------------------------------------------------------------
// Inputs (metadata order): h, norm, W, loop_weight, h_bias, src, dst, r
// ---------------------------------------------------------------------------
extern "C" void kernel_launch(void* const* d_in, const int* in_sizes, int n_in,
                              void* d_out, int out_size)
{
    const float* h    = (const float*)d_in[0];
    const float* norm = (const float*)d_in[1];
    const float* W    = (const float*)d_in[2];
    const float* lw   = (const float*)d_in[3];
    const float* bias = (const float*)d_in[4];
    const int*   src  = (const int*)d_in[5];
    const int*   dst  = (const int*)d_in[6];
    const int*   rel  = (const int*)d_in[7];
    float* out = (float*)d_out;

    int n_nodes = in_sizes[0] / DDIM;
    int n_edges = in_sizes[5];
    int n_rels  = in_sizes[2] / (DDIM * DDIM);

    int nb_nodes = (n_nodes + 255) / 256;
    int nb_edges = (n_edges + 255) / 256;

    // --- CSR build (int work, ~10us) ---
    zero_deg_kernel<<<nb_nodes, 256>>>(n_nodes);
    hist_kernel<<<nb_edges, 256>>>(dst, n_edges);
    scan_kernel<<<1, 1024>>>(n_nodes);
    cursor_kernel<<<nb_nodes, 256>>>(n_nodes);
    scatter_kernel<<<nb_edges, 256>>>(dst, n_edges);

    // --- hw[n][k][o] = h @ W[k] ---
    dim3 g_hw_grid((n_nodes + 63) / 64, n_rels);
    rgcn_gemm_kernel<<<g_hw_grid, 256>>>(h, W, nullptr, nullptr,
                                         n_nodes, n_rels * DDIM);

    // --- out = h @ loop_weight + bias (initializes d_out) ---
    dim3 g_loop((n_nodes + 63) / 64, 1);
    rgcn_gemm_kernel<<<g_loop, 256>>>(h, lw, bias, out, n_nodes, DDIM);

    // --- per-node aggregation + relu (no atomics) ---
    int nb_agg = (n_nodes * 32 + 255) / 256;
    agg_kernel<<<nb_agg, 256>>>(norm, src, rel, out, n_nodes);
}

// round 6
// speedup vs baseline: 2.0981x; 2.0981x over previous
#include <cuda_runtime.h>
#include <cstdint>

// Problem shape (fixed by dataset): N=50000 nodes, E=800000, K=8, D=64.
#define DDIM 64
#define MAX_NODES 50000
#define MAX_RELS 8

// Scratch: hw[n][k][o] (102.4 MB) and tf32-rounded W9 (W[0..7] + loop) 144 KB.
__device__ float g_hw[(size_t)MAX_NODES * MAX_RELS * DDIM];
__device__ float g_w9[9 * DDIM * DDIM];

__device__ __forceinline__ uint32_t rna_tf32(float v) {
    uint32_t u;
    asm("cvt.rna.tf32.f32 %0, %1;" : "=r"(u) : "f"(v));
    return u;
}

// m16n8k8 tf32 mma, fp32 accumulate (plain PTX ISA, sm_80+; compute_100-legal).
__device__ __forceinline__ void mma_tf32(float* c,
    uint32_t a0, uint32_t a1, uint32_t a2, uint32_t a3,
    uint32_t b0, uint32_t b1)
{
    asm volatile(
        "mma.sync.aligned.m16n8k8.row.col.f32.tf32.tf32.f32 "
        "{%0,%1,%2,%3}, {%4,%5,%6,%7}, {%8,%9}, {%0,%1,%2,%3};"
        : "+f"(c[0]), "+f"(c[1]), "+f"(c[2]), "+f"(c[3])
        : "r"(a0), "r"(a1), "r"(a2), "r"(a3), "r"(b0), "r"(b1));
}

// ---------------------------------------------------------------------------
// prep: W (8x64x64) ++ loop_weight (64x64) -> tf32-rna bit patterns in g_w9.
// ---------------------------------------------------------------------------
__global__ void prep_w9_kernel(const float* __restrict__ W,
                               const float* __restrict__ lw)
{
    int i = blockIdx.x * blockDim.x + threadIdx.x;
    if (i >= 9 * DDIM * DDIM) return;
    float v = (i < MAX_RELS * DDIM * DDIM) ? W[i] : lw[i - MAX_RELS * DDIM * DDIM];
    g_w9[i] = __uint_as_float(rna_tf32(v));
}

// ---------------------------------------------------------------------------
// Fused tensor-core GEMM, STATIC smem only (36 KB), 64-node tiles.
// Per tile: load/convert A once; loop rel = 0..8:
//   rel<8 -> g_hw[n][rel][:],  rel==8 -> d_out[n][:] + bias.
// Packing: pair (ks,t) -> {tf32(x[8ks+t]), tf32(x[8ks+t+4])}, row stride 36
// uint2 -> conflict-free lds.64 fragment loads.
// 8 warps: warp w = m-tile (w&3)*16, n-half (w>>2)*32. Warp tile m16 x n32.
// ---------------------------------------------------------------------------
#define A2_STRIDE 36

__global__ __launch_bounds__(256) void rgcn_gemm9_kernel(
    const float* __restrict__ h, const float* __restrict__ bias,
    float* __restrict__ out, int n_nodes)
{
    __shared__ uint2 A2[64 * A2_STRIDE];   // 18432 B
    __shared__ uint2 B2[64 * A2_STRIDE];   // 18432 B

    const int tid = threadIdx.x;
    const int gr0 = blockIdx.x * 64;

    // ---- Fill A tile: thread -> (row = tid>>2, quarter q = tid&3). ----
    {
        int row = tid >> 2;
        int q = tid & 3;            // handles ks = 2q, 2q+1
        int gr = gr0 + row;
        uint2* Arow = A2 + row * A2_STRIDE;
        if (gr < n_nodes) {
            const float4* hp = (const float4*)(h + (size_t)gr * DDIM);
#pragma unroll
            for (int kk = 0; kk < 2; ++kk) {
                int ks = 2 * q + kk;
                float4 v0 = hp[2 * ks];      // x[8ks .. 8ks+3]
                float4 v1 = hp[2 * ks + 1];  // x[8ks+4 .. 8ks+7]
                Arow[4 * ks + 0] = make_uint2(rna_tf32(v0.x), rna_tf32(v1.x));
                Arow[4 * ks + 1] = make_uint2(rna_tf32(v0.y), rna_tf32(v1.y));
                Arow[4 * ks + 2] = make_uint2(rna_tf32(v0.z), rna_tf32(v1.z));
                Arow[4 * ks + 3] = make_uint2(rna_tf32(v0.w), rna_tf32(v1.w));
            }
        } else {
#pragma unroll
            for (int kk = 0; kk < 2; ++kk) {
                int ks = 2 * q + kk;
                Arow[4 * ks + 0] = make_uint2(0u, 0u);
                Arow[4 * ks + 1] = make_uint2(0u, 0u);
                Arow[4 * ks + 2] = make_uint2(0u, 0u);
                Arow[4 * ks + 3] = make_uint2(0u, 0u);
            }
        }
    }

    const int wid = tid >> 5;
    const int lane = tid & 31;
    const int g = lane >> 2;       // groupID 0..7
    const int t = lane & 3;        // threadID_in_group 0..3
    const int m0 = (wid & 3) * 16;
    const int nbase = (wid >> 2) * 32;

    const uint2* ar0 = A2 + (m0 + g) * A2_STRIDE + t;
    const uint2* ar1 = A2 + (m0 + g + 8) * A2_STRIDE + t;
    const uint2* brb = B2 + (nbase + g) * A2_STRIDE + t;

    const int row_lo = gr0 + m0 + g;
    const int row_hi = row_lo + 8;

    for (int rel = 0; rel < 9; ++rel) {
        // ---- Fill B tile for this rel (2048 uint2, 8 per thread) ----
        __syncthreads();
        {
            const float* Wk = g_w9 + rel * DDIM * DDIM;
#pragma unroll
            for (int i = 0; i < 8; ++i) {
                int e = tid + i * 256;
                int n = e & 63;
                int p = e >> 6;            // 4*ks + tt
                int ks = p >> 2, tt = p & 3;
                uint32_t b0 = __float_as_uint(Wk[(8 * ks + tt) * DDIM + n]);
                uint32_t b1 = __float_as_uint(Wk[(8 * ks + tt + 4) * DDIM + n]);
                B2[n * A2_STRIDE + p] = make_uint2(b0, b1);
            }
        }
        __syncthreads();

        // ---- Compute: m16 x n32, K=64 ----
        float acc[4][4];
#pragma unroll
        for (int j = 0; j < 4; ++j)
#pragma unroll
            for (int qq = 0; qq < 4; ++qq) acc[j][qq] = 0.f;

#pragma unroll
        for (int ks = 0; ks < 8; ++ks) {
            uint2 A0 = ar0[4 * ks];    // {a0, a2}
            uint2 A1 = ar1[4 * ks];    // {a1, a3}
#pragma unroll
            for (int j = 0; j < 4; ++j) {
                uint2 B = brb[j * 8 * A2_STRIDE + 4 * ks];
                mma_tf32(acc[j], A0.x, A1.x, A0.y, A1.y, B.x, B.y);
            }
        }

        // ---- Writeback ----
        if (rel < 8) {
#pragma unroll
            for (int j = 0; j < 4; ++j) {
                int col = nbase + 8 * j + 2 * t;
                if (row_lo < n_nodes)
                    *(float2*)&g_hw[((size_t)row_lo * MAX_RELS + rel) * DDIM + col] =
                        make_float2(acc[j][0], acc[j][1]);
                if (row_hi < n_nodes)
                    *(float2*)&g_hw[((size_t)row_hi * MAX_RELS + rel) * DDIM + col] =
                        make_float2(acc[j][2], acc[j][3]);
            }
        } else {
#pragma unroll
            for (int j = 0; j < 4; ++j) {
                int col = nbase + 8 * j + 2 * t;
                float b0 = bias[col], b1 = bias[col + 1];
                if (row_lo < n_nodes)
                    *(float2*)&out[(size_t)row_lo * DDIM + col] =
                        make_float2(acc[j][0] + b0, acc[j][1] + b1);
                if (row_hi < n_nodes)
                    *(float2*)&out[(size_t)row_hi * DDIM + col] =
                        make_float2(acc[j][2] + b0, acc[j][3] + b1);
            }
        }
    }
}

// ---------------------------------------------------------------------------
// Edge scatter (R1 design, passed at 209us): 16 threads/edge, red.v4 atomics.
// ---------------------------------------------------------------------------
__global__ __launch_bounds__(256) void rgcn_edge_kernel(
    const float* __restrict__ norm, const int* __restrict__ src,
    const int* __restrict__ dst, const int* __restrict__ rel,
    float* __restrict__ out, int n_edges)
{
    int t = blockIdx.x * blockDim.x + threadIdx.x;
    int e = t >> 4;
    int lane = t & 15;
    if (e >= n_edges) return;

    int s  = src[e];
    int d_ = dst[e];
    int rr = rel[e];
    float nm = norm[e];

    const float4* row = (const float4*)(g_hw + ((size_t)s * MAX_RELS + rr) * DDIM);
    float4 v = row[lane];
    float mx = v.x * nm, my = v.y * nm, mz = v.z * nm, mw = v.w * nm;

    float* p = out + (size_t)d_ * DDIM + lane * 4;
    asm volatile("red.global.add.v4.f32 [%0], {%1, %2, %3, %4};"
                 :: "l"(p), "f"(mx), "f"(my), "f"(mz), "f"(mw)
                 : "memory");
}

__global__ __launch_bounds__(256) void rgcn_relu_kernel(float* __restrict__ out, int n4)
{
    int i = blockIdx.x * blockDim.x + threadIdx.x;
    if (i >= n4) return;
    float4 v = ((float4*)out)[i];
    v.x = fmaxf(v.x, 0.0f); v.y = fmaxf(v.y, 0.0f);
    v.z = fmaxf(v.z, 0.0f); v.w = fmaxf(v.w, 0.0f);
    ((float4*)out)[i] = v;
}

// ---------------------------------------------------------------------------
// Inputs (metadata order): h, norm, W, loop_weight, h_bias, src, dst, r
// ---------------------------------------------------------------------------
extern "C" void kernel_launch(void* const* d_in, const int* in_sizes, int n_in,
                              void* d_out, int out_size)
{
    const float* h    = (const float*)d_in[0];
    const float* norm = (const float*)d_in[1];
    const float* W    = (const float*)d_in[2];
    const float* lw   = (const float*)d_in[3];
    const float* bias = (const float*)d_in[4];
    const int*   src  = (const int*)d_in[5];
    const int*   dst  = (const int*)d_in[6];
    const int*   rel  = (const int*)d_in[7];
    float* out = (float*)d_out;

    int n_nodes = in_sizes[0] / DDIM;
    int n_edges = in_sizes[5];

    // 1) W ++ loop_weight -> tf32-rounded g_w9
    int wtot = 9 * DDIM * DDIM;
    prep_w9_kernel<<<(wtot + 255) / 256, 256>>>(W, lw);

    // 2) Fused tensor-core GEMM: g_hw (rels 0..7) + d_out = h@loop + bias
    int ntiles = (n_nodes + 63) / 64;
    rgcn_gemm9_kernel<<<ntiles, 256>>>(h, bias, out, n_nodes);

    // 3) edge scatter
    long long threads = (long long)n_edges * 16;
    rgcn_edge_kernel<<<(int)((threads + 255) / 256), 256>>>(norm, src, dst, rel, out, n_edges);

    // 4) ReLU
    int n4 = out_size / 4;
    rgcn_relu_kernel<<<(n4 + 255) / 256, 256>>>(out, n4);
}

// round 7
// speedup vs baseline: 2.1281x; 1.0143x over previous
#include <cuda_runtime.h>
#include <cstdint>

// Problem shape (fixed by dataset): N=50000 nodes, E=800000, K=8, D=64.
#define DDIM 64
#define MAX_NODES 50000
#define MAX_RELS 8
#define MAX_EDGES 800000
#define SCAN_CHUNK 1024

// Scratch: hw[n][k][o] (102.4 MB), tf32 W9, CSR arrays, packed edge records.
__device__ float g_hw[(size_t)MAX_NODES * MAX_RELS * DDIM];
__device__ float g_w9[9 * DDIM * DDIM];
__device__ int g_deg[MAX_NODES];
__device__ int g_rowptr[MAX_NODES + 1];
__device__ int g_cursor[MAX_NODES];
__device__ int g_blocksum[(MAX_NODES + SCAN_CHUNK - 1) / SCAN_CHUNK];
__device__ int g_chunkoff[(MAX_NODES + SCAN_CHUNK - 1) / SCAN_CHUNK];
__device__ int g_esr[MAX_EDGES];      // src*8 + rel, in CSR order
__device__ float g_enorm[MAX_EDGES];  // norm, in CSR order

__device__ __forceinline__ uint32_t rna_tf32(float v) {
    uint32_t u;
    asm("cvt.rna.tf32.f32 %0, %1;" : "=r"(u) : "f"(v));
    return u;
}

// m16n8k8 tf32 mma, fp32 accumulate.
__device__ __forceinline__ void mma_tf32(float* c,
    uint32_t a0, uint32_t a1, uint32_t a2, uint32_t a3,
    uint32_t b0, uint32_t b1)
{
    asm volatile(
        "mma.sync.aligned.m16n8k8.row.col.f32.tf32.tf32.f32 "
        "{%0,%1,%2,%3}, {%4,%5,%6,%7}, {%8,%9}, {%0,%1,%2,%3};"
        : "+f"(c[0]), "+f"(c[1]), "+f"(c[2]), "+f"(c[3])
        : "r"(a0), "r"(a1), "r"(a2), "r"(a3), "r"(b0), "r"(b1));
}

// ---------------------------------------------------------------------------
// prep: W ++ loop_weight -> tf32-rna in g_w9; also zero g_deg.
// ---------------------------------------------------------------------------
__global__ void prep_kernel(const float* __restrict__ W,
                            const float* __restrict__ lw, int n_nodes)
{
    int i = blockIdx.x * blockDim.x + threadIdx.x;
    if (i < 9 * DDIM * DDIM) {
        float v = (i < MAX_RELS * DDIM * DDIM) ? W[i] : lw[i - MAX_RELS * DDIM * DDIM];
        g_w9[i] = __uint_as_float(rna_tf32(v));
    }
    if (i < n_nodes) g_deg[i] = 0;
}

__global__ void hist_kernel(const int* __restrict__ dst, int n_edges)
{
    int e = blockIdx.x * blockDim.x + threadIdx.x;
    if (e < n_edges) atomicAdd(&g_deg[dst[e]], 1);
}

// Per-chunk reduction: blocksum[b] = sum of deg over chunk b.
__global__ __launch_bounds__(SCAN_CHUNK) void chunk_reduce_kernel(int n_nodes)
{
    __shared__ int sm[SCAN_CHUNK];
    int t = threadIdx.x;
    int i = blockIdx.x * SCAN_CHUNK + t;
    sm[t] = (i < n_nodes) ? g_deg[i] : 0;
    __syncthreads();
#pragma unroll
    for (int off = SCAN_CHUNK / 2; off > 0; off >>= 1) {
        if (t < off) sm[t] += sm[t + off];
        __syncthreads();
    }
    if (t == 0) g_blocksum[blockIdx.x] = sm[0];
}

// Tiny serial scan over chunk sums (nchunks ~ 49).
__global__ void scan_sums_kernel(int nchunks)
{
    if (threadIdx.x == 0) {
        int acc = 0;
        for (int i = 0; i < nchunks; ++i) {
            g_chunkoff[i] = acc;
            acc += g_blocksum[i];
        }
    }
}

// Per-chunk inclusive scan + chunk offset -> rowptr (exclusive) and cursor.
__global__ __launch_bounds__(SCAN_CHUNK) void chunk_scan_kernel(int n_nodes)
{
    __shared__ int sm[SCAN_CHUNK];
    int t = threadIdx.x;
    int i = blockIdx.x * SCAN_CHUNK + t;
    int v = (i < n_nodes) ? g_deg[i] : 0;
    sm[t] = v;
    __syncthreads();
#pragma unroll
    for (int off = 1; off < SCAN_CHUNK; off <<= 1) {
        int x = (t >= off) ? sm[t - off] : 0;
        __syncthreads();
        sm[t] += x;
        __syncthreads();
    }
    if (i < n_nodes) {
        int base = g_chunkoff[blockIdx.x];
        int excl = base + sm[t] - v;
        g_rowptr[i] = excl;
        g_cursor[i] = excl;
        if (i == n_nodes - 1) g_rowptr[n_nodes] = base + sm[t];
    }
}

// Scatter edges into CSR order as packed records (srcrel, norm).
__global__ void scatter_build_kernel(const int* __restrict__ src,
                                     const int* __restrict__ dst,
                                     const int* __restrict__ rel,
                                     const float* __restrict__ norm,
                                     int n_edges)
{
    int e = blockIdx.x * blockDim.x + threadIdx.x;
    if (e >= n_edges) return;
    int pos = atomicAdd(&g_cursor[dst[e]], 1);
    g_esr[pos] = src[e] * MAX_RELS + rel[e];
    g_enorm[pos] = norm[e];
}

// ---------------------------------------------------------------------------
// Fused tensor-core GEMM (unchanged from R6 / 145us kernel). Static smem.
// ---------------------------------------------------------------------------
#define A2_STRIDE 36

__global__ __launch_bounds__(256) void rgcn_gemm9_kernel(
    const float* __restrict__ h, const float* __restrict__ bias,
    float* __restrict__ out, int n_nodes)
{
    __shared__ uint2 A2[64 * A2_STRIDE];
    __shared__ uint2 B2[64 * A2_STRIDE];

    const int tid = threadIdx.x;
    const int gr0 = blockIdx.x * 64;

    {
        int row = tid >> 2;
        int q = tid & 3;
        int gr = gr0 + row;
        uint2* Arow = A2 + row * A2_STRIDE;
        if (gr < n_nodes) {
            const float4* hp = (const float4*)(h + (size_t)gr * DDIM);
#pragma unroll
            for (int kk = 0; kk < 2; ++kk) {
                int ks = 2 * q + kk;
                float4 v0 = hp[2 * ks];
                float4 v1 = hp[2 * ks + 1];
                Arow[4 * ks + 0] = make_uint2(rna_tf32(v0.x), rna_tf32(v1.x));
                Arow[4 * ks + 1] = make_uint2(rna_tf32(v0.y), rna_tf32(v1.y));
                Arow[4 * ks + 2] = make_uint2(rna_tf32(v0.z), rna_tf32(v1.z));
                Arow[4 * ks + 3] = make_uint2(rna_tf32(v0.w), rna_tf32(v1.w));
            }
        } else {
#pragma unroll
            for (int kk = 0; kk < 2; ++kk) {
                int ks = 2 * q + kk;
                Arow[4 * ks + 0] = make_uint2(0u, 0u);
                Arow[4 * ks + 1] = make_uint2(0u, 0u);
                Arow[4 * ks + 2] = make_uint2(0u, 0u);
                Arow[4 * ks + 3] = make_uint2(0u, 0u);
            }
        }
    }

    const int wid = tid >> 5;
    const int lane = tid & 31;
    const int g = lane >> 2;
    const int t = lane & 3;
    const int m0 = (wid & 3) * 16;
    const int nbase = (wid >> 2) * 32;

    const uint2* ar0 = A2 + (m0 + g) * A2_STRIDE + t;
    const uint2* ar1 = A2 + (m0 + g + 8) * A2_STRIDE + t;
    const uint2* brb = B2 + (nbase + g) * A2_STRIDE + t;

    const int row_lo = gr0 + m0 + g;
    const int row_hi = row_lo + 8;

    for (int rel = 0; rel < 9; ++rel) {
        __syncthreads();
        {
            const float* Wk = g_w9 + rel * DDIM * DDIM;
#pragma unroll
            for (int i = 0; i < 8; ++i) {
                int e = tid + i * 256;
                int n = e & 63;
                int p = e >> 6;
                int ks = p >> 2, tt = p & 3;
                uint32_t b0 = __float_as_uint(Wk[(8 * ks + tt) * DDIM + n]);
                uint32_t b1 = __float_as_uint(Wk[(8 * ks + tt + 4) * DDIM + n]);
                B2[n * A2_STRIDE + p] = make_uint2(b0, b1);
            }
        }
        __syncthreads();

        float acc[4][4];
#pragma unroll
        for (int j = 0; j < 4; ++j)
#pragma unroll
            for (int qq = 0; qq < 4; ++qq) acc[j][qq] = 0.f;

#pragma unroll
        for (int ks = 0; ks < 8; ++ks) {
            uint2 A0 = ar0[4 * ks];
            uint2 A1 = ar1[4 * ks];
#pragma unroll
            for (int j = 0; j < 4; ++j) {
                uint2 B = brb[j * 8 * A2_STRIDE + 4 * ks];
                mma_tf32(acc[j], A0.x, A1.x, A0.y, A1.y, B.x, B.y);
            }
        }

        if (rel < 8) {
#pragma unroll
            for (int j = 0; j < 4; ++j) {
                int col = nbase + 8 * j + 2 * t;
                if (row_lo < n_nodes)
                    *(float2*)&g_hw[((size_t)row_lo * MAX_RELS + rel) * DDIM + col] =
                        make_float2(acc[j][0], acc[j][1]);
                if (row_hi < n_nodes)
                    *(float2*)&g_hw[((size_t)row_hi * MAX_RELS + rel) * DDIM + col] =
                        make_float2(acc[j][2], acc[j][3]);
            }
        } else {
#pragma unroll
            for (int j = 0; j < 4; ++j) {
                int col = nbase + 8 * j + 2 * t;
                float b0 = bias[col], b1 = bias[col + 1];
                if (row_lo < n_nodes)
                    *(float2*)&out[(size_t)row_lo * DDIM + col] =
                        make_float2(acc[j][0] + b0, acc[j][1] + b1);
                if (row_hi < n_nodes)
                    *(float2*)&out[(size_t)row_hi * DDIM + col] =
                        make_float2(acc[j][2] + b0, acc[j][3] + b1);
            }
        }
    }
}

// ---------------------------------------------------------------------------
// Aggregation: one warp per dst node, CSR segment of packed records.
// acc = sum_e g_hw[srcrel_e * 64] * norm_e ; out = relu(out + acc). Fused relu.
// 4-way unrolled gathers for MLP.
// ---------------------------------------------------------------------------
__global__ __launch_bounds__(256) void agg_kernel(float* __restrict__ out, int n_nodes)
{
    int warp = (blockIdx.x * 256 + threadIdx.x) >> 5;
    int lane = threadIdx.x & 31;
    if (warp >= n_nodes) return;

    int beg = g_rowptr[warp];
    int end = g_rowptr[warp + 1];

    float ax = 0.f, ay = 0.f;
    int i = beg;
    for (; i + 3 < end; i += 4) {
        int sr0 = g_esr[i + 0], sr1 = g_esr[i + 1];
        int sr2 = g_esr[i + 2], sr3 = g_esr[i + 3];
        float n0 = g_enorm[i + 0], n1 = g_enorm[i + 1];
        float n2 = g_enorm[i + 2], n3 = g_enorm[i + 3];
        float2 v0 = ((const float2*)(g_hw + (size_t)sr0 * DDIM))[lane];
        float2 v1 = ((const float2*)(g_hw + (size_t)sr1 * DDIM))[lane];
        float2 v2 = ((const float2*)(g_hw + (size_t)sr2 * DDIM))[lane];
        float2 v3 = ((const float2*)(g_hw + (size_t)sr3 * DDIM))[lane];
        ax += v0.x * n0; ay += v0.y * n0;
        ax += v1.x * n1; ay += v1.y * n1;
        ax += v2.x * n2; ay += v2.y * n2;
        ax += v3.x * n3; ay += v3.y * n3;
    }
    for (; i < end; ++i) {
        int sr = g_esr[i];
        float nn = g_enorm[i];
        float2 v = ((const float2*)(g_hw + (size_t)sr * DDIM))[lane];
        ax += v.x * nn; ay += v.y * nn;
    }

    float2* o = (float2*)(out + (size_t)warp * DDIM);
    float2 base = o[lane];
    o[lane] = make_float2(fmaxf(base.x + ax, 0.0f), fmaxf(base.y + ay, 0.0f));
}

// ---------------------------------------------------------------------------
// Inputs (metadata order): h, norm, W, loop_weight, h_bias, src, dst, r
// ---------------------------------------------------------------------------
extern "C" void kernel_launch(void* const* d_in, const int* in_sizes, int n_in,
                              void* d_out, int out_size)
{
    const float* h    = (const float*)d_in[0];
    const float* norm = (const float*)d_in[1];
    const float* W    = (const float*)d_in[2];
    const float* lw   = (const float*)d_in[3];
    const float* bias = (const float*)d_in[4];
    const int*   src  = (const int*)d_in[5];
    const int*   dst  = (const int*)d_in[6];
    const int*   rel  = (const int*)d_in[7];
    float* out = (float*)d_out;

    int n_nodes = in_sizes[0] / DDIM;
    int n_edges = in_sizes[5];

    int nb_edges = (n_edges + 255) / 256;
    int nchunks = (n_nodes + SCAN_CHUNK - 1) / SCAN_CHUNK;

    // prep weights + zero degree counters
    int prep_n = (9 * DDIM * DDIM > n_nodes) ? 9 * DDIM * DDIM : n_nodes;
    prep_kernel<<<(prep_n + 255) / 256, 256>>>(W, lw, n_nodes);

    // CSR build
    hist_kernel<<<nb_edges, 256>>>(dst, n_edges);
    chunk_reduce_kernel<<<nchunks, SCAN_CHUNK>>>(n_nodes);
    scan_sums_kernel<<<1, 32>>>(nchunks);
    chunk_scan_kernel<<<nchunks, SCAN_CHUNK>>>(n_nodes);
    scatter_build_kernel<<<nb_edges, 256>>>(src, dst, rel, norm, n_edges);

    // Fused tensor-core GEMM: g_hw (rels 0..7) + d_out = h@loop + bias
    int ntiles = (n_nodes + 63) / 64;
    rgcn_gemm9_kernel<<<ntiles, 256>>>(h, bias, out, n_nodes);

    // Per-node CSR aggregation + fused ReLU (no fp atomics)
    int nb_agg = (n_nodes * 32 + 255) / 256;
    agg_kernel<<<nb_agg, 256>>>(out, n_nodes);
}